// round 6
// baseline (speedup 1.0000x reference)
#include <cuda_runtime.h>
#include <cstdint>

#define NN 20000
#define EE 640000
#define HH 128
#define TILE_E 256
#define EDGE_GRID (EE / TILE_E) // 2500 exact
#define SZ 132                  // padded smem stride (words)
#define GB2 157                 // ceil(20000/128)
#define TG_SMEM (3 * HH * SZ * 4)

// ---------------- scratch ----------------
__device__ float g_U[NN * HH];
__device__ float g_V[NN * HH];
__device__ float g_Zsum[NN * HH];
__device__ float g_M[NN * HH];
__device__ float g_T[NN * HH];
__device__ float g_h0[NN * HH];
__device__ float g_h1[NN * HH];
__device__ float g_x0[NN * 3];
__device__ float g_x1[NN * 3];
__device__ float g_deg[NN];
__device__ float g_D[HH * HH];    // eW2 @ cW1
__device__ float g_dvec[HH];      // eb2 @ cW1 + cb1
__device__ float g_Wb[6 * HH * HH];  // tf32 "big" halves of weights
__device__ float g_Ws[6 * HH * HH];  // tf32 "small" residuals
__device__ float g_zero[HH];         // stays zero

__device__ __forceinline__ uint32_t f2tf32(float f) {
    uint32_t r;
    asm("cvt.rna.tf32.f32 %0, %1;" : "=r"(r) : "f"(f));
    return r;
}

// ---------------- degree ----------------
__global__ void deg_kernel(const int* __restrict__ erow) {
    int e = blockIdx.x * 256 + threadIdx.x;
    if (e < EE) atomicAdd(&g_deg[erow[e]], 1.0f);
}

// ---------------- D = eW2 @ cW1, dvec = eb2 @ cW1 + cb1 ----------------
__global__ void precompD_kernel(const float* __restrict__ eW2, const float* __restrict__ cW1,
                                const float* __restrict__ eb2, const float* __restrict__ cb1) {
    int a = blockIdx.x, j = threadIdx.x;
    float s = 0.f;
#pragma unroll 8
    for (int m = 0; m < HH; m++)
        s = fmaf(__ldg(&eW2[a * HH + m]), __ldg(&cW1[m * HH + j]), s);
    g_D[a * HH + j] = s;
    if (a == 0) {
        float t = __ldg(&cb1[j]);
#pragma unroll 8
        for (int m = 0; m < HH; m++)
            t = fmaf(__ldg(&eb2[m]), __ldg(&cW1[m * HH + j]), t);
        g_dvec[j] = t;
    }
}

// ---------------- split weights into tf32 big + residual ----------------
// mats: 0=eW1a 1=eW1b 2=eW2 3=nW1a 4=nW1b 5=nW2
__global__ void split_kernel(const float* __restrict__ eW1, const float* __restrict__ eW2,
                             const float* __restrict__ nW1, const float* __restrict__ nW2) {
    int j = threadIdx.x;
    int k = blockIdx.x & 127;
    int mat = blockIdx.x >> 7;
    const float* src;
    switch (mat) {
        case 0: src = eW1 + k * HH; break;
        case 1: src = eW1 + (128 + k) * HH; break;
        case 2: src = eW2 + k * HH; break;
        case 3: src = nW1 + k * HH; break;
        case 4: src = nW1 + (128 + k) * HH; break;
        default: src = nW2 + k * HH; break;
    }
    float w = __ldg(src + j);
    uint32_t wb = f2tf32(w);
    float wbf = __uint_as_float(wb);
    float ws = w - wbf;
    g_Wb[mat * (HH * HH) + k * HH + j] = wbf;
    g_Ws[mat * (HH * HH) + k * HH + j] = __uint_as_float(f2tf32(ws));
}

// ---------------- h0 = h @ emb_W + emb_b ----------------
__global__ void embed_kernel(const float* __restrict__ hin, const float* __restrict__ W,
                             const float* __restrict__ b) {
    int r = blockIdx.x, j = threadIdx.x;
    __shared__ float sh[16];
    if (j < 16) sh[j] = hin[r * 16 + j];
    __syncthreads();
    float acc = __ldg(&b[j]);
#pragma unroll
    for (int k = 0; k < 16; k++)
        acc = fmaf(sh[k], __ldg(&W[k * HH + j]), acc);
    g_h0[r * HH + j] = acc;
}

// ---------------- tensor-core node GEMM (3xTF32, near-fp32 exact) ----------------
// C[128rows x 128cols] = act( A1@W1 [+ A2@W2] + bias*(rowscale) [+ resid] )
template <bool TWO, bool RELU, bool RESID, bool ROWSCALE>
__global__ void __launch_bounds__(256, 1)
tgemm(const float* __restrict__ A1, const float* __restrict__ W1b, const float* __restrict__ W1s,
      const float* __restrict__ A2, const float* __restrict__ W2b, const float* __restrict__ W2s,
      const float* __restrict__ bias, const float* __restrict__ rowscale,
      const float* __restrict__ resid, float* __restrict__ C, int nrows) {
    extern __shared__ float smem[];
    float* sA  = smem;              // 128 x SZ (fp32)
    float* sWb = sA + HH * SZ;      // 128 x SZ (tf32 bits)
    float* sWs = sWb + HH * SZ;     // 128 x SZ (tf32 bits)

    const int tid = threadIdx.x;
    const int lane = tid & 31;
    const int warp = tid >> 5;
    const int qr = lane >> 2;
    const int lr = lane & 3;
    const int r0 = blockIdx.x * 128;
    const int m0 = warp * 16;

    float c0[16], c1[16], c2[16], c3[16];
#pragma unroll
    for (int nt = 0; nt < 16; nt++) { c0[nt] = 0.f; c1[nt] = 0.f; c2[nt] = 0.f; c3[nt] = 0.f; }

#pragma unroll
    for (int stage = 0; stage < (TWO ? 2 : 1); stage++) {
        const float* A  = (TWO && stage) ? A2 : A1;
        const float* Wb = (TWO && stage) ? W2b : W1b;
        const float* Ws = (TWO && stage) ? W2s : W1s;
        if (stage) __syncthreads();

        // load A tile (row-clamped), W tiles
#pragma unroll
        for (int it = 0; it < 16; it++) {
            int l = tid + 256 * it;
            int row = l >> 5, c4 = l & 31;
            int gr = r0 + row;
            if (gr >= nrows) gr = nrows - 1;
            float4 a = __ldg((const float4*)(A + (size_t)gr * HH) + c4);
            *(float4*)(sA + row * SZ + c4 * 4) = a;
            float4 wb = __ldg((const float4*)(Wb + row * HH) + c4);
            *(float4*)(sWb + row * SZ + c4 * 4) = wb;
            float4 ws = __ldg((const float4*)(Ws + row * HH) + c4);
            *(float4*)(sWs + row * SZ + c4 * 4) = ws;
        }
        __syncthreads();

        const float* za = sA + (m0 + qr) * SZ;
#pragma unroll
        for (int kt = 0; kt < 16; kt++) {
            const int k0 = kt * 8 + lr;
            float af0 = za[k0];
            float af1 = za[8 * SZ + k0];
            float af2 = za[k0 + 4];
            float af3 = za[8 * SZ + k0 + 4];
            uint32_t ab0 = f2tf32(af0), ab1 = f2tf32(af1);
            uint32_t ab2 = f2tf32(af2), ab3 = f2tf32(af3);
            uint32_t as0 = f2tf32(af0 - __uint_as_float(ab0));
            uint32_t as1 = f2tf32(af1 - __uint_as_float(ab1));
            uint32_t as2 = f2tf32(af2 - __uint_as_float(ab2));
            uint32_t as3 = f2tf32(af3 - __uint_as_float(ab3));
            const float* wbp = sWb + (kt * 8 + lr) * SZ + qr;
            const float* wsp = sWs + (kt * 8 + lr) * SZ + qr;
#pragma unroll
            for (int nt = 0; nt < 16; nt++) {
                uint32_t bb0 = __float_as_uint(wbp[nt * 8]);
                uint32_t bb1 = __float_as_uint(wbp[4 * SZ + nt * 8]);
                uint32_t bs0 = __float_as_uint(wsp[nt * 8]);
                uint32_t bs1 = __float_as_uint(wsp[4 * SZ + nt * 8]);
                asm volatile(
                    "mma.sync.aligned.m16n8k8.row.col.f32.tf32.tf32.f32 "
                    "{%0,%1,%2,%3}, {%4,%5,%6,%7}, {%8,%9}, {%0,%1,%2,%3};"
                    : "+f"(c0[nt]), "+f"(c1[nt]), "+f"(c2[nt]), "+f"(c3[nt])
                    : "r"(ab0), "r"(ab1), "r"(ab2), "r"(ab3), "r"(bb0), "r"(bb1));
                asm volatile(
                    "mma.sync.aligned.m16n8k8.row.col.f32.tf32.tf32.f32 "
                    "{%0,%1,%2,%3}, {%4,%5,%6,%7}, {%8,%9}, {%0,%1,%2,%3};"
                    : "+f"(c0[nt]), "+f"(c1[nt]), "+f"(c2[nt]), "+f"(c3[nt])
                    : "r"(ab0), "r"(ab1), "r"(ab2), "r"(ab3), "r"(bs0), "r"(bs1));
                asm volatile(
                    "mma.sync.aligned.m16n8k8.row.col.f32.tf32.tf32.f32 "
                    "{%0,%1,%2,%3}, {%4,%5,%6,%7}, {%8,%9}, {%0,%1,%2,%3};"
                    : "+f"(c0[nt]), "+f"(c1[nt]), "+f"(c2[nt]), "+f"(c3[nt])
                    : "r"(as0), "r"(as1), "r"(as2), "r"(as3), "r"(bb0), "r"(bb1));
            }
        }
    }

    // epilogue
    const int row0 = r0 + m0 + qr;
    const int row1 = row0 + 8;
#pragma unroll
    for (int nt = 0; nt < 16; nt++) {
        int j = nt * 8 + 2 * lr;
        float b0 = __ldg(&bias[j]), b1 = __ldg(&bias[j + 1]);
        if (row0 < nrows) {
            float t0 = ROWSCALE ? __ldg(&rowscale[row0]) : 1.f;
            float v0 = c0[nt] + (ROWSCALE ? t0 * b0 : b0);
            float v1 = c1[nt] + (ROWSCALE ? t0 * b1 : b1);
            if (RELU) { v0 = fmaxf(v0, 0.f); v1 = fmaxf(v1, 0.f); }
            if (RESID) {
                float2 rr = *(const float2*)(resid + (size_t)row0 * HH + j);
                v0 += rr.x; v1 += rr.y;
            }
            float2 vv; vv.x = v0; vv.y = v1;
            *(float2*)(C + (size_t)row0 * HH + j) = vv;
        }
        if (row1 < nrows) {
            float t1 = ROWSCALE ? __ldg(&rowscale[row1]) : 1.f;
            float v2 = c2[nt] + (ROWSCALE ? t1 * b0 : b0);
            float v3 = c3[nt] + (ROWSCALE ? t1 * b1 : b1);
            if (RELU) { v2 = fmaxf(v2, 0.f); v3 = fmaxf(v3, 0.f); }
            if (RESID) {
                float2 rr = *(const float2*)(resid + (size_t)row1 * HH + j);
                v2 += rr.x; v3 += rr.y;
            }
            float2 vv; vv.x = v2; vv.y = v3;
            *(float2*)(C + (size_t)row1 * HH + j) = vv;
        }
    }
}

// ---------------- fused edge kernel: 256-edge tiles, tf32 mma with B-frag reuse ----------------
#define EDGE_SMEM_BYTES ((HH * SZ + TILE_E * SZ + 3 * HH + 6 * TILE_E) * 4)

__global__ void __launch_bounds__(256, 1)
edge_kernel(const int* __restrict__ erow, const int* __restrict__ ecol,
            const float* __restrict__ xin, const float* __restrict__ w3,
            const float* __restrict__ cW2, const float* __restrict__ cb2,
            float* __restrict__ xout) {
    extern __shared__ float sm[];
    float* Ds    = sm;                       // 128*132 tf32
    float* zs    = Ds + HH * SZ;             // 256*132 tf32, [e][k]
    float* sdv   = zs + TILE_E * SZ;
    float* sc2   = sdv + HH;
    float* sw3   = sc2 + HH;
    float* srd   = sw3 + HH;
    float* srelx = srd + TILE_E;
    float* srely = srelx + TILE_E;
    float* srelz = srely + TILE_E;
    int*   ser   = (int*)(srelz + TILE_E);
    int*   sec   = ser + TILE_E;

    const int tid  = threadIdx.x;
    const int lane = tid & 31;
    const int warp = tid >> 5;

    {
        const float4* D4 = (const float4*)g_D;
#pragma unroll
        for (int it = 0; it < 16; it++) {
            int l = tid + 256 * it;
            int row = l >> 5;
            int c4  = l & 31;
            float4 d = D4[l];
            uint4 t;
            t.x = f2tf32(d.x); t.y = f2tf32(d.y);
            t.z = f2tf32(d.z); t.w = f2tf32(d.w);
            *(uint4*)(Ds + row * SZ + c4 * 4) = t;
        }
    }
    if (tid < HH) {
        sdv[tid] = g_dvec[tid];
        sc2[tid] = __ldg(&cW2[tid]);
        sw3[tid] = __ldg(&w3[tid]);
    }
    const float cb2v = __ldg(cb2);

    const int e0 = blockIdx.x * TILE_E;

    {
        int e = e0 + tid;
        int r = erow[e];
        int c = ecol[e];
        float dx = __ldg(&xin[3 * r + 0]) - __ldg(&xin[3 * c + 0]);
        float dy = __ldg(&xin[3 * r + 1]) - __ldg(&xin[3 * c + 1]);
        float dz = __ldg(&xin[3 * r + 2]) - __ldg(&xin[3 * c + 2]);
        ser[tid] = r; sec[tid] = c;
        srelx[tid] = dx; srely[tid] = dy; srelz[tid] = dz;
        srd[tid] = dx * dx + dy * dy + dz * dz;
    }
    __syncthreads();

    {
        float4 w = ((const float4*)sw3)[lane];
#pragma unroll 4
        for (int ee = 0; ee < 32; ee++) {
            int eL = warp * 32 + ee;
            int r = ser[eL], c = sec[eL];
            float rd = srd[eL];
            const float4* Up = (const float4*)(g_U + (size_t)r * HH);
            const float4* Vp = (const float4*)(g_V + (size_t)c * HH);
            float4 u = __ldg(Up + lane);
            float4 v = __ldg(Vp + lane);
            float4 z;
            z.x = fmaxf(u.x + v.x + rd * w.x, 0.f);
            z.y = fmaxf(u.y + v.y + rd * w.y, 0.f);
            z.z = fmaxf(u.z + v.z + rd * w.z, 0.f);
            z.w = fmaxf(u.w + v.w + rd * w.w, 0.f);
            float* zp = g_Zsum + (size_t)r * HH + lane * 4;
            asm volatile("red.global.add.v4.f32 [%0], {%1, %2, %3, %4};"
                         :: "l"(zp), "f"(z.x), "f"(z.y), "f"(z.z), "f"(z.w)
                         : "memory");
            uint4 t;
            t.x = f2tf32(z.x); t.y = f2tf32(z.y);
            t.z = f2tf32(z.z); t.w = f2tf32(z.w);
            *(uint4*)(zs + eL * SZ + lane * 4) = t;
        }
    }
    __syncthreads();

    const int qr = lane >> 2;
    const int lr = lane & 3;
    const int m0 = warp * 32;

    float cA0[16], cA1[16], cA2[16], cA3[16];
    float cB0[16], cB1[16], cB2[16], cB3[16];
#pragma unroll
    for (int nt = 0; nt < 16; nt++) {
        cA0[nt] = 0.f; cA1[nt] = 0.f; cA2[nt] = 0.f; cA3[nt] = 0.f;
        cB0[nt] = 0.f; cB1[nt] = 0.f; cB2[nt] = 0.f; cB3[nt] = 0.f;
    }

    const uint32_t* Du = (const uint32_t*)Ds;
    const uint32_t* z0 = (const uint32_t*)zs + (m0 + qr) * SZ;
    const uint32_t* z1 = z0 + 16 * SZ;

#pragma unroll
    for (int kt = 0; kt < 16; kt++) {
        const int k0 = kt * 8 + lr;
        uint32_t a00 = z0[k0];
        uint32_t a01 = z0[8 * SZ + k0];
        uint32_t a02 = z0[k0 + 4];
        uint32_t a03 = z0[8 * SZ + k0 + 4];
        uint32_t a10 = z1[k0];
        uint32_t a11 = z1[8 * SZ + k0];
        uint32_t a12 = z1[k0 + 4];
        uint32_t a13 = z1[8 * SZ + k0 + 4];
        const uint32_t* db = Du + (lr + kt * 8) * SZ + qr;
#pragma unroll
        for (int nt = 0; nt < 16; nt++) {
            uint32_t b0 = db[nt * 8];
            uint32_t b1 = db[4 * SZ + nt * 8];
            asm volatile(
                "mma.sync.aligned.m16n8k8.row.col.f32.tf32.tf32.f32 "
                "{%0,%1,%2,%3}, {%4,%5,%6,%7}, {%8,%9}, {%0,%1,%2,%3};"
                : "+f"(cA0[nt]), "+f"(cA1[nt]), "+f"(cA2[nt]), "+f"(cA3[nt])
                : "r"(a00), "r"(a01), "r"(a02), "r"(a03), "r"(b0), "r"(b1));
            asm volatile(
                "mma.sync.aligned.m16n8k8.row.col.f32.tf32.tf32.f32 "
                "{%0,%1,%2,%3}, {%4,%5,%6,%7}, {%8,%9}, {%0,%1,%2,%3};"
                : "+f"(cB0[nt]), "+f"(cB1[nt]), "+f"(cB2[nt]), "+f"(cB3[nt])
                : "r"(a10), "r"(a11), "r"(a12), "r"(a13), "r"(b0), "r"(b1));
        }
    }

    float s0 = 0.f, s1 = 0.f, s2 = 0.f, s3 = 0.f;
#pragma unroll
    for (int nt = 0; nt < 16; nt++) {
        int j0 = nt * 8 + 2 * lr;
        float dva = sdv[j0], dvb = sdv[j0 + 1];
        float wa = sc2[j0], wb = sc2[j0 + 1];
        s0 = fmaf(fmaxf(cA0[nt] + dva, 0.f), wa, s0);
        s0 = fmaf(fmaxf(cA1[nt] + dvb, 0.f), wb, s0);
        s1 = fmaf(fmaxf(cA2[nt] + dva, 0.f), wa, s1);
        s1 = fmaf(fmaxf(cA3[nt] + dvb, 0.f), wb, s1);
        s2 = fmaf(fmaxf(cB0[nt] + dva, 0.f), wa, s2);
        s2 = fmaf(fmaxf(cB1[nt] + dvb, 0.f), wb, s2);
        s3 = fmaf(fmaxf(cB2[nt] + dva, 0.f), wa, s3);
        s3 = fmaf(fmaxf(cB3[nt] + dvb, 0.f), wb, s3);
    }
#pragma unroll
    for (int off = 1; off <= 2; off <<= 1) {
        s0 += __shfl_xor_sync(0xffffffffu, s0, off);
        s1 += __shfl_xor_sync(0xffffffffu, s1, off);
        s2 += __shfl_xor_sync(0xffffffffu, s2, off);
        s3 += __shfl_xor_sync(0xffffffffu, s3, off);
    }

    if (lr == 0) {
        int eIdx[4] = {m0 + qr, m0 + qr + 8, m0 + 16 + qr, m0 + 24 + qr};
        float sv[4] = {s0, s1, s2, s3};
#pragma unroll
        for (int i = 0; i < 4; i++) {
            int eL = eIdx[i];
            float a = sv[i] + cb2v;
            int r = ser[eL];
            atomicAdd(&xout[3 * r + 0], a * srelx[eL]);
            atomicAdd(&xout[3 * r + 1], a * srely[eL]);
            atomicAdd(&xout[3 * r + 2], a * srelz[eL]);
        }
    }
}

// ---------------- host launch ----------------
extern "C" void kernel_launch(void* const* d_in, const int* in_sizes, int n_in,
                              void* d_out, int out_size) {
    const float* h    = (const float*)d_in[0];
    const float* x    = (const float*)d_in[1];
    const int*   ei   = (const int*)d_in[2];
    const float* embW = (const float*)d_in[3];
    const float* embb = (const float*)d_in[4];
    const float* eW1  = (const float*)d_in[5];
    const float* eb1  = (const float*)d_in[6];
    const float* eW2  = (const float*)d_in[7];
    const float* eb2  = (const float*)d_in[8];
    const float* nW1  = (const float*)d_in[9];
    const float* nb1  = (const float*)d_in[10];
    const float* nW2  = (const float*)d_in[11];
    const float* nb2  = (const float*)d_in[12];
    const float* cW1  = (const float*)d_in[13];
    const float* cb1  = (const float*)d_in[14];
    const float* cW2  = (const float*)d_in[15];
    const float* cb2  = (const float*)d_in[16];
    const int* erow = ei;
    const int* ecol = ei + EE;
    float* out = (float*)d_out;

    void* p;
    float *pU, *pV, *pZ, *pM, *pT, *pH0, *pH1, *pX0, *pX1, *pDeg, *pWb, *pWs, *pZero;
    cudaGetSymbolAddress(&p, g_U);    pU  = (float*)p;
    cudaGetSymbolAddress(&p, g_V);    pV  = (float*)p;
    cudaGetSymbolAddress(&p, g_Zsum); pZ  = (float*)p;
    cudaGetSymbolAddress(&p, g_M);    pM  = (float*)p;
    cudaGetSymbolAddress(&p, g_T);    pT  = (float*)p;
    cudaGetSymbolAddress(&p, g_h0);   pH0 = (float*)p;
    cudaGetSymbolAddress(&p, g_h1);   pH1 = (float*)p;
    cudaGetSymbolAddress(&p, g_x0);   pX0 = (float*)p;
    cudaGetSymbolAddress(&p, g_x1);   pX1 = (float*)p;
    cudaGetSymbolAddress(&p, g_deg);  pDeg = (float*)p;
    cudaGetSymbolAddress(&p, g_Wb);   pWb = (float*)p;
    cudaGetSymbolAddress(&p, g_Ws);   pWs = (float*)p;
    cudaGetSymbolAddress(&p, g_zero); pZero = (float*)p;

    cudaFuncSetAttribute(edge_kernel, cudaFuncAttributeMaxDynamicSharedMemorySize,
                         EDGE_SMEM_BYTES);
    cudaFuncSetAttribute(tgemm<false, false, false, false>,
                         cudaFuncAttributeMaxDynamicSharedMemorySize, TG_SMEM);
    cudaFuncSetAttribute(tgemm<false, false, false, true>,
                         cudaFuncAttributeMaxDynamicSharedMemorySize, TG_SMEM);
    cudaFuncSetAttribute(tgemm<true, true, false, false>,
                         cudaFuncAttributeMaxDynamicSharedMemorySize, TG_SMEM);
    cudaFuncSetAttribute(tgemm<false, false, true, false>,
                         cudaFuncAttributeMaxDynamicSharedMemorySize, TG_SMEM);

    // ---- per-call precompute ----
    cudaMemsetAsync(pDeg, 0, NN * sizeof(float));
    deg_kernel<<<EE / 256, 256>>>(erow);
    precompD_kernel<<<HH, HH>>>(eW2, cW1, eb2, cb1);
    split_kernel<<<6 * HH, HH>>>(eW1, eW2, nW1, nW2);
    embed_kernel<<<NN, HH>>>(h, embW, embb);
    cudaMemcpyAsync(pX0, x, NN * 3 * sizeof(float), cudaMemcpyDeviceToDevice);

    const int MSZ = HH * HH;

    for (int l = 0; l < 2; l++) {
        const float* hi = (l == 0) ? pH0 : pH1;
        float*       ho = (l == 0) ? pH1 : out;
        const float* xi = (l == 0) ? pX0 : pX1;
        float*       xo = (l == 0) ? pX1 : out + (size_t)NN * HH;

        cudaMemsetAsync(pZ, 0, (size_t)NN * HH * sizeof(float));
        cudaMemcpyAsync(xo, xi, NN * 3 * sizeof(float), cudaMemcpyDeviceToDevice);

        // U = hi @ eW1a + eb1
        tgemm<false, false, false, false><<<GB2, 256, TG_SMEM>>>(
            hi, pWb + 0 * MSZ, pWs + 0 * MSZ, nullptr, nullptr, nullptr,
            eb1, nullptr, nullptr, pU, NN);
        // V = hi @ eW1b
        tgemm<false, false, false, false><<<GB2, 256, TG_SMEM>>>(
            hi, pWb + 1 * MSZ, pWs + 1 * MSZ, nullptr, nullptr, nullptr,
            pZero, nullptr, nullptr, pV, NN);
        // fused edge pass
        edge_kernel<<<EDGE_GRID, 256, EDGE_SMEM_BYTES>>>(erow, ecol, xi, eW1 + 256 * HH,
                                                         cW2, cb2, xo);
        // M = Zsum @ eW2 + deg * eb2
        tgemm<false, false, false, true><<<GB2, 256, TG_SMEM>>>(
            pZ, pWb + 2 * MSZ, pWs + 2 * MSZ, nullptr, nullptr, nullptr,
            eb2, pDeg, nullptr, pM, NN);
        // T = relu(hi @ nW1a + M @ nW1b + nb1)
        tgemm<true, true, false, false><<<GB2, 256, TG_SMEM>>>(
            hi, pWb + 3 * MSZ, pWs + 3 * MSZ, pM, pWb + 4 * MSZ, pWs + 4 * MSZ,
            nb1, nullptr, nullptr, pT, NN);
        // ho = hi + T @ nW2 + nb2
        tgemm<false, false, true, false><<<GB2, 256, TG_SMEM>>>(
            pT, pWb + 5 * MSZ, pWs + 5 * MSZ, nullptr, nullptr, nullptr,
            nb2, nullptr, hi, ho, NN);
    }
    (void)in_sizes; (void)n_in; (void)out_size;
}

// round 7
// speedup vs baseline: 1.0279x; 1.0279x over previous
#include <cuda_runtime.h>
#include <cstdint>

#define NN 20000
#define EE 640000
#define HH 128
#define TILE_E 256
#define EDGE_GRID (EE / TILE_E) // 2500 exact
#define RPB 32
#define SZ 132                  // zs stride (words): A-frags conflict-free
#define SZD 136                 // Ds stride (words): B-frags conflict-free

// ---------------- scratch ----------------
__device__ float g_U[NN * HH];
__device__ float g_V[NN * HH];
__device__ float g_Zsum[NN * HH];
__device__ float g_M[NN * HH];
__device__ float g_T[NN * HH];
__device__ float g_h0[NN * HH];
__device__ float g_h1[NN * HH];
__device__ float g_x0[NN * 3];
__device__ float g_x1[NN * 3];
__device__ float g_deg[NN];
__device__ float g_D[HH * HH];    // eW2 @ cW1
__device__ float g_dvec[HH];      // eb2 @ cW1 + cb1
__device__ float g_Wuv[HH * 256]; // [k][0:128]=eW1a, [k][128:256]=eW1b
__device__ float g_buv[256];

__device__ __forceinline__ uint32_t f2tf32(float f) {
    uint32_t r;
    asm("cvt.rna.tf32.f32 %0, %1;" : "=r"(r) : "f"(f));
    return r;
}

// ---------------- degree ----------------
__global__ void deg_kernel(const int* __restrict__ erow) {
    int e = blockIdx.x * 256 + threadIdx.x;
    if (e < EE) atomicAdd(&g_deg[erow[e]], 1.0f);
}

// ---------------- D = eW2 @ cW1, dvec = eb2 @ cW1 + cb1 ----------------
__global__ void precompD_kernel(const float* __restrict__ eW2, const float* __restrict__ cW1,
                                const float* __restrict__ eb2, const float* __restrict__ cb1) {
    int a = blockIdx.x, j = threadIdx.x;
    float s = 0.f;
#pragma unroll 8
    for (int m = 0; m < HH; m++)
        s = fmaf(__ldg(&eW2[a * HH + m]), __ldg(&cW1[m * HH + j]), s);
    g_D[a * HH + j] = s;
    if (a == 0) {
        float t = __ldg(&cb1[j]);
#pragma unroll 8
        for (int m = 0; m < HH; m++)
            t = fmaf(__ldg(&eb2[m]), __ldg(&cW1[m * HH + j]), t);
        g_dvec[j] = t;
    }
}

__global__ void wuv_kernel(const float* __restrict__ eW1, const float* __restrict__ eb1) {
    int k = blockIdx.x, j = threadIdx.x;
    g_Wuv[k * 256 + j] = eW1[k * HH + j];
    g_Wuv[k * 256 + 128 + j] = eW1[(HH + k) * HH + j];
    if (k == 0) {
        g_buv[j] = eb1[j];
        g_buv[128 + j] = 0.f;
    }
}

// ---------------- embed: 128 rows per block, W in smem ----------------
__global__ void __launch_bounds__(128)
embed_kernel(const float* __restrict__ hin, const float* __restrict__ W,
             const float* __restrict__ b, int nrows) {
    __shared__ float sW[16 * HH];
    __shared__ float sH[128 * 16];
    const int tid = threadIdx.x;
    const int r0 = blockIdx.x * 128;
#pragma unroll
    for (int it = 0; it < 16; it++)
        sW[tid + it * 128] = __ldg(&W[tid + it * 128]);
    // load 128 rows x 16 cols of h (float4: 128*4 loads)
#pragma unroll
    for (int it = 0; it < 4; it++) {
        int l = tid + it * 128;          // 0..511 float4 slots
        int row = l >> 2, c4 = l & 3;
        int gr = r0 + row;
        if (gr >= nrows) gr = nrows - 1;
        float4 v = __ldg((const float4*)(hin + (size_t)gr * 16) + c4);
        *(float4*)(sH + row * 16 + c4 * 4) = v;
    }
    __syncthreads();
    const float bj = __ldg(&b[tid]);
#pragma unroll 1
    for (int rr = 0; rr < 128; rr++) {
        int gr = r0 + rr;
        if (gr >= nrows) break;
        float acc = bj;
#pragma unroll
        for (int k = 0; k < 16; k++)
            acc = fmaf(sH[rr * 16 + k], sW[k * HH + tid], acc);
        g_h0[(size_t)gr * HH + tid] = acc;
    }
}

// ---------------- U|V fused node GEMM (256 output cols) ----------------
__global__ void __launch_bounds__(256)
gemm_uv(const float* __restrict__ A1, float* __restrict__ U, float* __restrict__ V) {
    __shared__ float sA[HH][36];
    const int r0 = blockIdx.x * RPB;
    const int j = threadIdx.x & 127;
    const int half = threadIdx.x >> 7;
#pragma unroll
    for (int ii = 0; ii < 16; ii++) {
        int i = half * 16 + ii;
        sA[j][i] = A1[(size_t)(r0 + i) * HH + j];
    }
    __syncthreads();

    const int jp = threadIdx.x;
    float acc[RPB];
    float b = g_buv[jp];
#pragma unroll
    for (int i = 0; i < RPB; i++) acc[i] = b;

#pragma unroll 4
    for (int k = 0; k < HH; k++) {
        float w = g_Wuv[k * 256 + jp];
#pragma unroll
        for (int i = 0; i < RPB; i += 4) {
            float4 a = *(const float4*)&sA[k][i];
            acc[i + 0] = fmaf(a.x, w, acc[i + 0]);
            acc[i + 1] = fmaf(a.y, w, acc[i + 1]);
            acc[i + 2] = fmaf(a.z, w, acc[i + 2]);
            acc[i + 3] = fmaf(a.w, w, acc[i + 3]);
        }
    }
    float* outp = (jp < 128) ? U : V;
    int jo = jp & 127;
#pragma unroll
    for (int i = 0; i < RPB; i++)
        outp[(size_t)(r0 + i) * HH + jo] = acc[i];
}

// ---------------- generic node GEMM ----------------
template <bool TWO, bool RELU, bool RESID, bool ROWSCALE>
__global__ void __launch_bounds__(128)
gemm128(const float* __restrict__ A1, const float* __restrict__ W1,
        const float* __restrict__ A2, const float* __restrict__ W2,
        const float* __restrict__ bias, const float* __restrict__ rowscale,
        const float* __restrict__ resid, float* __restrict__ C) {
    __shared__ float sA[HH][36];
    __shared__ float sB[TWO ? HH : 1][TWO ? 36 : 1];
    const int r0 = blockIdx.x * RPB;
    const int j = threadIdx.x;

#pragma unroll 8
    for (int i = 0; i < RPB; i++) sA[j][i] = A1[(size_t)(r0 + i) * HH + j];
    if (TWO) {
#pragma unroll 8
        for (int i = 0; i < RPB; i++) sB[j][i] = A2[(size_t)(r0 + i) * HH + j];
    }
    __syncthreads();

    float b = bias ? __ldg(&bias[j]) : 0.f;
    float acc[RPB];
#pragma unroll
    for (int i = 0; i < RPB; i++)
        acc[i] = ROWSCALE ? __ldg(&rowscale[r0 + i]) * b : b;

#pragma unroll 4
    for (int k = 0; k < HH; k++) {
        float w = __ldg(&W1[k * HH + j]);
#pragma unroll
        for (int i = 0; i < RPB; i += 4) {
            float4 a = *(const float4*)&sA[k][i];
            acc[i + 0] = fmaf(a.x, w, acc[i + 0]);
            acc[i + 1] = fmaf(a.y, w, acc[i + 1]);
            acc[i + 2] = fmaf(a.z, w, acc[i + 2]);
            acc[i + 3] = fmaf(a.w, w, acc[i + 3]);
        }
    }
    if (TWO) {
#pragma unroll 4
        for (int k = 0; k < HH; k++) {
            float w = __ldg(&W2[k * HH + j]);
#pragma unroll
            for (int i = 0; i < RPB; i += 4) {
                float4 a = *(const float4*)&sB[k][i];
                acc[i + 0] = fmaf(a.x, w, acc[i + 0]);
                acc[i + 1] = fmaf(a.y, w, acc[i + 1]);
                acc[i + 2] = fmaf(a.z, w, acc[i + 2]);
                acc[i + 3] = fmaf(a.w, w, acc[i + 3]);
            }
        }
    }
#pragma unroll
    for (int i = 0; i < RPB; i++) {
        float v = acc[i];
        if (RELU) v = fmaxf(v, 0.f);
        if (RESID) v += resid[(size_t)(r0 + i) * HH + j];
        C[(size_t)(r0 + i) * HH + j] = v;
    }
}

// ---------------- fused edge kernel ----------------
#define EDGE_SMEM_BYTES ((HH * SZD + TILE_E * SZ + 3 * HH + 6 * TILE_E) * 4)

__global__ void __launch_bounds__(256, 1)
edge_kernel(const int* __restrict__ erow, const int* __restrict__ ecol,
            const float* __restrict__ xin, const float* __restrict__ w3,
            const float* __restrict__ cW2, const float* __restrict__ cb2,
            float* __restrict__ xout) {
    extern __shared__ float sm[];
    float* Ds    = sm;                       // 128 x SZD tf32
    float* zs    = Ds + HH * SZD;            // 256 x SZ tf32, [e][k]
    float* sdv   = zs + TILE_E * SZ;
    float* sc2   = sdv + HH;
    float* sw3   = sc2 + HH;
    float* srd   = sw3 + HH;
    float* srelx = srd + TILE_E;
    float* srely = srelx + TILE_E;
    float* srelz = srely + TILE_E;
    int*   ser   = (int*)(srelz + TILE_E);
    int*   sec   = ser + TILE_E;

    const int tid  = threadIdx.x;
    const int lane = tid & 31;
    const int warp = tid >> 5;

    {
        const float4* D4 = (const float4*)g_D;
#pragma unroll
        for (int it = 0; it < 16; it++) {
            int l = tid + 256 * it;
            int row = l >> 5;
            int c4  = l & 31;
            float4 d = D4[l];
            uint4 t;
            t.x = f2tf32(d.x); t.y = f2tf32(d.y);
            t.z = f2tf32(d.z); t.w = f2tf32(d.w);
            *(uint4*)(Ds + row * SZD + c4 * 4) = t;
        }
    }
    if (tid < HH) {
        sdv[tid] = g_dvec[tid];
        sc2[tid] = __ldg(&cW2[tid]);
        sw3[tid] = __ldg(&w3[tid]);
    }
    const float cb2v = __ldg(cb2);

    const int e0 = blockIdx.x * TILE_E;

    {
        int e = e0 + tid;
        int r = erow[e];
        int c = ecol[e];
        float dx = __ldg(&xin[3 * r + 0]) - __ldg(&xin[3 * c + 0]);
        float dy = __ldg(&xin[3 * r + 1]) - __ldg(&xin[3 * c + 1]);
        float dz = __ldg(&xin[3 * r + 2]) - __ldg(&xin[3 * c + 2]);
        ser[tid] = r; sec[tid] = c;
        srelx[tid] = dx; srely[tid] = dy; srelz[tid] = dz;
        srd[tid] = dx * dx + dy * dy + dz * dz;
    }
    __syncthreads();

    {
        float4 w = ((const float4*)sw3)[lane];
#pragma unroll 4
        for (int ee = 0; ee < 32; ee++) {
            int eL = warp * 32 + ee;
            int r = ser[eL], c = sec[eL];
            float rd = srd[eL];
            const float4* Up = (const float4*)(g_U + (size_t)r * HH);
            const float4* Vp = (const float4*)(g_V + (size_t)c * HH);
            float4 u = __ldg(Up + lane);
            float4 v = __ldg(Vp + lane);
            float4 z;
            z.x = fmaxf(u.x + v.x + rd * w.x, 0.f);
            z.y = fmaxf(u.y + v.y + rd * w.y, 0.f);
            z.z = fmaxf(u.z + v.z + rd * w.z, 0.f);
            z.w = fmaxf(u.w + v.w + rd * w.w, 0.f);
            float* zp = g_Zsum + (size_t)r * HH + lane * 4;
            asm volatile("red.global.add.v4.f32 [%0], {%1, %2, %3, %4};"
                         :: "l"(zp), "f"(z.x), "f"(z.y), "f"(z.z), "f"(z.w)
                         : "memory");
            uint4 t;
            t.x = f2tf32(z.x); t.y = f2tf32(z.y);
            t.z = f2tf32(z.z); t.w = f2tf32(z.w);
            *(uint4*)(zs + eL * SZ + lane * 4) = t;
        }
    }
    __syncthreads();

    const int qr = lane >> 2;
    const int lr = lane & 3;
    const int m0 = warp * 32;

    float cA0[16], cA1[16], cA2[16], cA3[16];
    float cB0[16], cB1[16], cB2[16], cB3[16];
#pragma unroll
    for (int nt = 0; nt < 16; nt++) {
        cA0[nt] = 0.f; cA1[nt] = 0.f; cA2[nt] = 0.f; cA3[nt] = 0.f;
        cB0[nt] = 0.f; cB1[nt] = 0.f; cB2[nt] = 0.f; cB3[nt] = 0.f;
    }

    const uint32_t* Du = (const uint32_t*)Ds;
    const uint32_t* z0 = (const uint32_t*)zs + (m0 + qr) * SZ;
    const uint32_t* z1 = z0 + 16 * SZ;

#pragma unroll
    for (int kt = 0; kt < 16; kt++) {
        const int k0 = kt * 8 + lr;
        uint32_t a00 = z0[k0];
        uint32_t a01 = z0[8 * SZ + k0];
        uint32_t a02 = z0[k0 + 4];
        uint32_t a03 = z0[8 * SZ + k0 + 4];
        uint32_t a10 = z1[k0];
        uint32_t a11 = z1[8 * SZ + k0];
        uint32_t a12 = z1[k0 + 4];
        uint32_t a13 = z1[8 * SZ + k0 + 4];
        const uint32_t* db = Du + (lr + kt * 8) * SZD + qr;
#pragma unroll
        for (int nt = 0; nt < 16; nt++) {
            uint32_t b0 = db[nt * 8];
            uint32_t b1 = db[4 * SZD + nt * 8];
            asm volatile(
                "mma.sync.aligned.m16n8k8.row.col.f32.tf32.tf32.f32 "
                "{%0,%1,%2,%3}, {%4,%5,%6,%7}, {%8,%9}, {%0,%1,%2,%3};"
                : "+f"(cA0[nt]), "+f"(cA1[nt]), "+f"(cA2[nt]), "+f"(cA3[nt])
                : "r"(a00), "r"(a01), "r"(a02), "r"(a03), "r"(b0), "r"(b1));
            asm volatile(
                "mma.sync.aligned.m16n8k8.row.col.f32.tf32.tf32.f32 "
                "{%0,%1,%2,%3}, {%4,%5,%6,%7}, {%8,%9}, {%0,%1,%2,%3};"
                : "+f"(cB0[nt]), "+f"(cB1[nt]), "+f"(cB2[nt]), "+f"(cB3[nt])
                : "r"(a10), "r"(a11), "r"(a12), "r"(a13), "r"(b0), "r"(b1));
        }
    }

    float s0 = 0.f, s1 = 0.f, s2 = 0.f, s3 = 0.f;
#pragma unroll
    for (int nt = 0; nt < 16; nt++) {
        int j0 = nt * 8 + 2 * lr;
        float dva = sdv[j0], dvb = sdv[j0 + 1];
        float wa = sc2[j0], wb = sc2[j0 + 1];
        s0 = fmaf(fmaxf(cA0[nt] + dva, 0.f), wa, s0);
        s0 = fmaf(fmaxf(cA1[nt] + dvb, 0.f), wb, s0);
        s1 = fmaf(fmaxf(cA2[nt] + dva, 0.f), wa, s1);
        s1 = fmaf(fmaxf(cA3[nt] + dvb, 0.f), wb, s1);
        s2 = fmaf(fmaxf(cB0[nt] + dva, 0.f), wa, s2);
        s2 = fmaf(fmaxf(cB1[nt] + dvb, 0.f), wb, s2);
        s3 = fmaf(fmaxf(cB2[nt] + dva, 0.f), wa, s3);
        s3 = fmaf(fmaxf(cB3[nt] + dvb, 0.f), wb, s3);
    }
#pragma unroll
    for (int off = 1; off <= 2; off <<= 1) {
        s0 += __shfl_xor_sync(0xffffffffu, s0, off);
        s1 += __shfl_xor_sync(0xffffffffu, s1, off);
        s2 += __shfl_xor_sync(0xffffffffu, s2, off);
        s3 += __shfl_xor_sync(0xffffffffu, s3, off);
    }

    if (lr == 0) {
        int eIdx[4] = {m0 + qr, m0 + qr + 8, m0 + 16 + qr, m0 + 24 + qr};
        float sv[4] = {s0, s1, s2, s3};
#pragma unroll
        for (int i = 0; i < 4; i++) {
            int eL = eIdx[i];
            float a = sv[i] + cb2v;
            int r = ser[eL];
            atomicAdd(&xout[3 * r + 0], a * srelx[eL]);
            atomicAdd(&xout[3 * r + 1], a * srely[eL]);
            atomicAdd(&xout[3 * r + 2], a * srelz[eL]);
        }
    }
}

// ---------------- host launch ----------------
extern "C" void kernel_launch(void* const* d_in, const int* in_sizes, int n_in,
                              void* d_out, int out_size) {
    const float* h    = (const float*)d_in[0];
    const float* x    = (const float*)d_in[1];
    const int*   ei   = (const int*)d_in[2];
    const float* embW = (const float*)d_in[3];
    const float* embb = (const float*)d_in[4];
    const float* eW1  = (const float*)d_in[5];
    const float* eb1  = (const float*)d_in[6];
    const float* eW2  = (const float*)d_in[7];
    const float* eb2  = (const float*)d_in[8];
    const float* nW1  = (const float*)d_in[9];
    const float* nb1  = (const float*)d_in[10];
    const float* nW2  = (const float*)d_in[11];
    const float* nb2  = (const float*)d_in[12];
    const float* cW1  = (const float*)d_in[13];
    const float* cb1  = (const float*)d_in[14];
    const float* cW2  = (const float*)d_in[15];
    const float* cb2  = (const float*)d_in[16];
    const int* erow = ei;
    const int* ecol = ei + EE;
    float* out = (float*)d_out;

    void* p;
    float *pU, *pV, *pZ, *pM, *pT, *pH0, *pH1, *pX0, *pX1, *pDeg;
    cudaGetSymbolAddress(&p, g_U);    pU  = (float*)p;
    cudaGetSymbolAddress(&p, g_V);    pV  = (float*)p;
    cudaGetSymbolAddress(&p, g_Zsum); pZ  = (float*)p;
    cudaGetSymbolAddress(&p, g_M);    pM  = (float*)p;
    cudaGetSymbolAddress(&p, g_T);    pT  = (float*)p;
    cudaGetSymbolAddress(&p, g_h0);   pH0 = (float*)p;
    cudaGetSymbolAddress(&p, g_h1);   pH1 = (float*)p;
    cudaGetSymbolAddress(&p, g_x0);   pX0 = (float*)p;
    cudaGetSymbolAddress(&p, g_x1);   pX1 = (float*)p;
    cudaGetSymbolAddress(&p, g_deg);  pDeg = (float*)p;

    cudaFuncSetAttribute(edge_kernel, cudaFuncAttributeMaxDynamicSharedMemorySize,
                         EDGE_SMEM_BYTES);

    // ---- per-call precompute ----
    cudaMemsetAsync(pDeg, 0, NN * sizeof(float));
    deg_kernel<<<EE / 256, 256>>>(erow);
    precompD_kernel<<<HH, HH>>>(eW2, cW1, eb2, cb1);
    wuv_kernel<<<HH, HH>>>(eW1, eb1);
    embed_kernel<<<157, 128>>>(h, embW, embb, NN);
    cudaMemcpyAsync(pX0, x, NN * 3 * sizeof(float), cudaMemcpyDeviceToDevice);

    const int GB = NN / RPB;  // 625

    for (int l = 0; l < 2; l++) {
        const float* hi = (l == 0) ? pH0 : pH1;
        float*       ho = (l == 0) ? pH1 : out;
        const float* xi = (l == 0) ? pX0 : pX1;
        float*       xo = (l == 0) ? pX1 : out + (size_t)NN * HH;

        cudaMemsetAsync(pZ, 0, (size_t)NN * HH * sizeof(float));
        cudaMemcpyAsync(xo, xi, NN * 3 * sizeof(float), cudaMemcpyDeviceToDevice);

        gemm_uv<<<GB, 256>>>(hi, pU, pV);
        edge_kernel<<<EDGE_GRID, 256, EDGE_SMEM_BYTES>>>(erow, ecol, xi, eW1 + 256 * HH,
                                                         cW2, cb2, xo);
        gemm128<false, false, false, true><<<GB, HH>>>(pZ, eW2, nullptr, nullptr,
                                                       eb2, pDeg, nullptr, pM);
        gemm128<true, true, false, false><<<GB, HH>>>(hi, nW1, pM, nW1 + HH * HH,
                                                      nb1, nullptr, nullptr, pT);
        gemm128<false, false, true, false><<<GB, HH>>>(pT, nW2, nullptr, nullptr,
                                                       nb2, nullptr, hi, ho);
    }
    (void)in_sizes; (void)n_in; (void)out_size;
}

// round 8
// speedup vs baseline: 1.0462x; 1.0178x over previous
#include <cuda_runtime.h>
#include <cstdint>

#define NN 20000
#define EE 640000
#define HH 128
#define NTILES 5000             // tiles of 128 edges
#define GRIDP 148               // persistent blocks
#define RPB 32
#define SZ 132                  // zs stride (words): A-frags conflict-free
#define SZD 136                 // Ds stride (words): B-frags conflict-free

// ---------------- scratch ----------------
__device__ float g_U[NN * HH];
__device__ float g_V[NN * HH];
__device__ float g_Zsum[NN * HH];
__device__ float g_M[NN * HH];
__device__ float g_T[NN * HH];
__device__ float g_h0[NN * HH];
__device__ float g_h1[NN * HH];
__device__ float g_x0[NN * 3];
__device__ float g_x1[NN * 3];
__device__ float g_deg[NN];
__device__ float g_D[HH * HH];    // eW2 @ cW1
__device__ float g_dvec[HH];      // eb2 @ cW1 + cb1
__device__ float g_Wuv[HH * 256]; // [k][0:128]=eW1a, [k][128:256]=eW1b
__device__ float g_buv[256];

__device__ __forceinline__ uint32_t f2tf32(float f) {
    uint32_t r;
    asm("cvt.rna.tf32.f32 %0, %1;" : "=r"(r) : "f"(f));
    return r;
}

// ---------------- degree ----------------
__global__ void deg_kernel(const int* __restrict__ erow) {
    int e = blockIdx.x * 256 + threadIdx.x;
    if (e < EE) atomicAdd(&g_deg[erow[e]], 1.0f);
}

// ---------------- D = eW2 @ cW1, dvec = eb2 @ cW1 + cb1 ----------------
__global__ void precompD_kernel(const float* __restrict__ eW2, const float* __restrict__ cW1,
                                const float* __restrict__ eb2, const float* __restrict__ cb1) {
    int a = blockIdx.x, j = threadIdx.x;
    float s = 0.f;
#pragma unroll 8
    for (int m = 0; m < HH; m++)
        s = fmaf(__ldg(&eW2[a * HH + m]), __ldg(&cW1[m * HH + j]), s);
    g_D[a * HH + j] = s;
    if (a == 0) {
        float t = __ldg(&cb1[j]);
#pragma unroll 8
        for (int m = 0; m < HH; m++)
            t = fmaf(__ldg(&eb2[m]), __ldg(&cW1[m * HH + j]), t);
        g_dvec[j] = t;
    }
}

__global__ void wuv_kernel(const float* __restrict__ eW1, const float* __restrict__ eb1) {
    int k = blockIdx.x, j = threadIdx.x;
    g_Wuv[k * 256 + j] = eW1[k * HH + j];
    g_Wuv[k * 256 + 128 + j] = eW1[(HH + k) * HH + j];
    if (k == 0) {
        g_buv[j] = eb1[j];
        g_buv[128 + j] = 0.f;
    }
}

// ---------------- embed ----------------
__global__ void __launch_bounds__(128)
embed_kernel(const float* __restrict__ hin, const float* __restrict__ W,
             const float* __restrict__ b, int nrows) {
    __shared__ float sW[16 * HH];
    __shared__ float sH[128 * 16];
    const int tid = threadIdx.x;
    const int r0 = blockIdx.x * 128;
#pragma unroll
    for (int it = 0; it < 16; it++)
        sW[tid + it * 128] = __ldg(&W[tid + it * 128]);
#pragma unroll
    for (int it = 0; it < 4; it++) {
        int l = tid + it * 128;
        int row = l >> 2, c4 = l & 3;
        int gr = r0 + row;
        if (gr >= nrows) gr = nrows - 1;
        float4 v = __ldg((const float4*)(hin + (size_t)gr * 16) + c4);
        *(float4*)(sH + row * 16 + c4 * 4) = v;
    }
    __syncthreads();
    const float bj = __ldg(&b[tid]);
#pragma unroll 1
    for (int rr = 0; rr < 128; rr++) {
        int gr = r0 + rr;
        if (gr >= nrows) break;
        float acc = bj;
#pragma unroll
        for (int k = 0; k < 16; k++)
            acc = fmaf(sH[rr * 16 + k], sW[k * HH + tid], acc);
        g_h0[(size_t)gr * HH + tid] = acc;
    }
}

// ---------------- U|V fused node GEMM ----------------
__global__ void __launch_bounds__(256)
gemm_uv(const float* __restrict__ A1, float* __restrict__ U, float* __restrict__ V) {
    __shared__ float sA[HH][36];
    const int r0 = blockIdx.x * RPB;
    const int j = threadIdx.x & 127;
    const int half = threadIdx.x >> 7;
#pragma unroll
    for (int ii = 0; ii < 16; ii++) {
        int i = half * 16 + ii;
        sA[j][i] = A1[(size_t)(r0 + i) * HH + j];
    }
    __syncthreads();

    const int jp = threadIdx.x;
    float acc[RPB];
    float b = g_buv[jp];
#pragma unroll
    for (int i = 0; i < RPB; i++) acc[i] = b;

#pragma unroll 4
    for (int k = 0; k < HH; k++) {
        float w = g_Wuv[k * 256 + jp];
#pragma unroll
        for (int i = 0; i < RPB; i += 4) {
            float4 a = *(const float4*)&sA[k][i];
            acc[i + 0] = fmaf(a.x, w, acc[i + 0]);
            acc[i + 1] = fmaf(a.y, w, acc[i + 1]);
            acc[i + 2] = fmaf(a.z, w, acc[i + 2]);
            acc[i + 3] = fmaf(a.w, w, acc[i + 3]);
        }
    }
    float* outp = (jp < 128) ? U : V;
    int jo = jp & 127;
#pragma unroll
    for (int i = 0; i < RPB; i++)
        outp[(size_t)(r0 + i) * HH + jo] = acc[i];
}

// ---------------- generic node GEMM ----------------
template <bool TWO, bool RELU, bool RESID, bool ROWSCALE>
__global__ void __launch_bounds__(128)
gemm128(const float* __restrict__ A1, const float* __restrict__ W1,
        const float* __restrict__ A2, const float* __restrict__ W2,
        const float* __restrict__ bias, const float* __restrict__ rowscale,
        const float* __restrict__ resid, float* __restrict__ C) {
    __shared__ float sA[HH][36];
    __shared__ float sB[TWO ? HH : 1][TWO ? 36 : 1];
    const int r0 = blockIdx.x * RPB;
    const int j = threadIdx.x;

#pragma unroll 8
    for (int i = 0; i < RPB; i++) sA[j][i] = A1[(size_t)(r0 + i) * HH + j];
    if (TWO) {
#pragma unroll 8
        for (int i = 0; i < RPB; i++) sB[j][i] = A2[(size_t)(r0 + i) * HH + j];
    }
    __syncthreads();

    float b = bias ? __ldg(&bias[j]) : 0.f;
    float acc[RPB];
#pragma unroll
    for (int i = 0; i < RPB; i++)
        acc[i] = ROWSCALE ? __ldg(&rowscale[r0 + i]) * b : b;

#pragma unroll 4
    for (int k = 0; k < HH; k++) {
        float w = __ldg(&W1[k * HH + j]);
#pragma unroll
        for (int i = 0; i < RPB; i += 4) {
            float4 a = *(const float4*)&sA[k][i];
            acc[i + 0] = fmaf(a.x, w, acc[i + 0]);
            acc[i + 1] = fmaf(a.y, w, acc[i + 1]);
            acc[i + 2] = fmaf(a.z, w, acc[i + 2]);
            acc[i + 3] = fmaf(a.w, w, acc[i + 3]);
        }
    }
    if (TWO) {
#pragma unroll 4
        for (int k = 0; k < HH; k++) {
            float w = __ldg(&W2[k * HH + j]);
#pragma unroll
            for (int i = 0; i < RPB; i += 4) {
                float4 a = *(const float4*)&sB[k][i];
                acc[i + 0] = fmaf(a.x, w, acc[i + 0]);
                acc[i + 1] = fmaf(a.y, w, acc[i + 1]);
                acc[i + 2] = fmaf(a.z, w, acc[i + 2]);
                acc[i + 3] = fmaf(a.w, w, acc[i + 3]);
            }
        }
    }
#pragma unroll
    for (int i = 0; i < RPB; i++) {
        float v = acc[i];
        if (RELU) v = fmaxf(v, 0.f);
        if (RESID) v += resid[(size_t)(r0 + i) * HH + j];
        C[(size_t)(r0 + i) * HH + j] = v;
    }
}

// ---------------- persistent, pipelined fused edge kernel ----------------
// smem: Ds(128xSZD) + zs(2 x 128xSZ) + consts + geo(x3 buffers)
#define EDGE_SMEM_BYTES ((HH * SZD + 2 * HH * SZ + 3 * HH + 6 * 3 * HH) * 4)

__global__ void __launch_bounds__(256, 1)
edge_kernel(const int* __restrict__ erow, const int* __restrict__ ecol,
            const float* __restrict__ xin, const float* __restrict__ w3,
            const float* __restrict__ cW2, const float* __restrict__ cb2,
            float* __restrict__ xout) {
    extern __shared__ float sm[];
    float* Ds    = sm;                        // 128 x SZD (tf32 bits)
    float* zs    = Ds + HH * SZD;             // 2 x 128 x SZ (tf32 bits)
    float* sdv   = zs + 2 * HH * SZ;          // 128
    float* sc2   = sdv + HH;                  // 128
    float* sw3   = sc2 + HH;                  // 128
    float* srd   = sw3 + HH;                  // 3 x 128
    float* srelx = srd + 3 * HH;
    float* srely = srelx + 3 * HH;
    float* srelz = srely + 3 * HH;
    int*   ser   = (int*)(srelz + 3 * HH);
    int*   sec   = ser + 3 * HH;

    const int tid  = threadIdx.x;
    const int lane = tid & 31;
    const int warp = tid >> 5;

    // ---- load D (once per block) ----
    {
        const float4* D4 = (const float4*)g_D;
#pragma unroll
        for (int it = 0; it < 16; it++) {
            int l = tid + 256 * it;
            int row = l >> 5;
            int c4  = l & 31;
            float4 d = D4[l];
            uint4 t;
            t.x = f2tf32(d.x); t.y = f2tf32(d.y);
            t.z = f2tf32(d.z); t.w = f2tf32(d.w);
            *(uint4*)(Ds + row * SZD + c4 * 4) = t;
        }
    }
    if (tid < HH) {
        sdv[tid] = g_dvec[tid];
        sc2[tid] = __ldg(&cW2[tid]);
        sw3[tid] = __ldg(&w3[tid]);
    }
    const float cb2v = __ldg(cb2);

    const int b = blockIdx.x;
    const int ntile = (NTILES - b + GRIDP - 1) / GRIDP;

    // ---- geometry stage: tile i -> geo buffer i%3 (tid<128) ----
    auto geom = [&](int i) {
        if (tid < 128) {
            int e = (b + i * GRIDP) * 128 + tid;
            int buf = (i % 3) * 128 + tid;
            int r = __ldg(&erow[e]);
            int c = __ldg(&ecol[e]);
            float dx = __ldg(&xin[3 * r + 0]) - __ldg(&xin[3 * c + 0]);
            float dy = __ldg(&xin[3 * r + 1]) - __ldg(&xin[3 * c + 1]);
            float dz = __ldg(&xin[3 * r + 2]) - __ldg(&xin[3 * c + 2]);
            ser[buf] = r; sec[buf] = c;
            srelx[buf] = dx; srely[buf] = dy; srelz[buf] = dz;
            srd[buf] = dx * dx + dy * dy + dz * dz;
        }
    };

    // ---- phase A: z1 for tile i -> zs buffer i&1 (warp-local rows) ----
    auto phaseA = [&](int i) {
        const int gbuf = (i % 3) * 128;
        float* z = zs + (i & 1) * HH * SZ;
        float4 w = ((const float4*)sw3)[lane];
#pragma unroll 4
        for (int ee = 0; ee < 16; ee++) {
            int eL = warp * 16 + ee;
            int r = ser[gbuf + eL], c = sec[gbuf + eL];
            float rd = srd[gbuf + eL];
            float4 u = __ldg((const float4*)(g_U + (size_t)r * HH) + lane);
            float4 v = __ldg((const float4*)(g_V + (size_t)c * HH) + lane);
            float4 zz;
            zz.x = fmaxf(u.x + v.x + rd * w.x, 0.f);
            zz.y = fmaxf(u.y + v.y + rd * w.y, 0.f);
            zz.z = fmaxf(u.z + v.z + rd * w.z, 0.f);
            zz.w = fmaxf(u.w + v.w + rd * w.w, 0.f);
            float* zp = g_Zsum + (size_t)r * HH + lane * 4;
            asm volatile("red.global.add.v4.f32 [%0], {%1, %2, %3, %4};"
                         :: "l"(zp), "f"(zz.x), "f"(zz.y), "f"(zz.z), "f"(zz.w)
                         : "memory");
            uint4 t;
            t.x = f2tf32(zz.x); t.y = f2tf32(zz.y);
            t.z = f2tf32(zz.z); t.w = f2tf32(zz.w);
            *(uint4*)(z + eL * SZ + lane * 4) = t;
        }
    };

    // ---- phase B+C: mma + alpha + scatter for tile i ----
    auto phaseBC = [&](int i) {
        const int gbuf = (i % 3) * 128;
        const float* z = zs + (i & 1) * HH * SZ;
        const int qr = lane >> 2;
        const int lr = lane & 3;
        const int m0 = warp * 16;

        float c0[16], c1[16], c2[16], c3[16];
#pragma unroll
        for (int nt = 0; nt < 16; nt++) { c0[nt] = 0.f; c1[nt] = 0.f; c2[nt] = 0.f; c3[nt] = 0.f; }

        const uint32_t* Du = (const uint32_t*)Ds;
        const uint32_t* z0 = (const uint32_t*)z + (m0 + qr) * SZ;
        const uint32_t* z1 = z0 + 8 * SZ;

#pragma unroll
        for (int kt = 0; kt < 16; kt++) {
            const int k0 = kt * 8 + lr;
            uint32_t a0 = z0[k0];
            uint32_t a1 = z1[k0];
            uint32_t a2 = z0[k0 + 4];
            uint32_t a3 = z1[k0 + 4];
            const uint32_t* db = Du + (lr + kt * 8) * SZD + qr;
#pragma unroll
            for (int nt = 0; nt < 16; nt++) {
                uint32_t b0 = db[nt * 8];
                uint32_t b1 = db[4 * SZD + nt * 8];
                asm volatile(
                    "mma.sync.aligned.m16n8k8.row.col.f32.tf32.tf32.f32 "
                    "{%0,%1,%2,%3}, {%4,%5,%6,%7}, {%8,%9}, {%0,%1,%2,%3};"
                    : "+f"(c0[nt]), "+f"(c1[nt]), "+f"(c2[nt]), "+f"(c3[nt])
                    : "r"(a0), "r"(a1), "r"(a2), "r"(a3), "r"(b0), "r"(b1));
            }
        }

        float s0 = 0.f, s1 = 0.f;
#pragma unroll
        for (int nt = 0; nt < 16; nt++) {
            int j0 = nt * 8 + 2 * lr;
            float dva = sdv[j0], dvb = sdv[j0 + 1];
            float wa = sc2[j0], wb = sc2[j0 + 1];
            s0 = fmaf(fmaxf(c0[nt] + dva, 0.f), wa, s0);
            s0 = fmaf(fmaxf(c1[nt] + dvb, 0.f), wb, s0);
            s1 = fmaf(fmaxf(c2[nt] + dva, 0.f), wa, s1);
            s1 = fmaf(fmaxf(c3[nt] + dvb, 0.f), wb, s1);
        }
        s0 += __shfl_xor_sync(0xffffffffu, s0, 1);
        s0 += __shfl_xor_sync(0xffffffffu, s0, 2);
        s1 += __shfl_xor_sync(0xffffffffu, s1, 1);
        s1 += __shfl_xor_sync(0xffffffffu, s1, 2);

        if (lr == 0) {
            int eA = m0 + qr;
            int eB = eA + 8;
            float aA = s0 + cb2v;
            float aB = s1 + cb2v;
            int rA = ser[gbuf + eA], rB = ser[gbuf + eB];
            atomicAdd(&xout[3 * rA + 0], aA * srelx[gbuf + eA]);
            atomicAdd(&xout[3 * rA + 1], aA * srely[gbuf + eA]);
            atomicAdd(&xout[3 * rA + 2], aA * srelz[gbuf + eA]);
            atomicAdd(&xout[3 * rB + 0], aB * srelx[gbuf + eB]);
            atomicAdd(&xout[3 * rB + 1], aB * srely[gbuf + eB]);
            atomicAdd(&xout[3 * rB + 2], aB * srelz[gbuf + eB]);
        }
    };

    // ---- pipelined main loop ----
    if (ntile > 0) geom(0);
    __syncthreads();
    if (ntile > 0) phaseA(0);
    if (ntile > 1) geom(1);
    __syncthreads();
    for (int i = 0; i < ntile; i++) {
        if (i + 1 < ntile) phaseA(i + 1);
        if (i + 2 < ntile) geom(i + 2);
        phaseBC(i);
        __syncthreads();
    }
}

// ---------------- host launch ----------------
extern "C" void kernel_launch(void* const* d_in, const int* in_sizes, int n_in,
                              void* d_out, int out_size) {
    const float* h    = (const float*)d_in[0];
    const float* x    = (const float*)d_in[1];
    const int*   ei   = (const int*)d_in[2];
    const float* embW = (const float*)d_in[3];
    const float* embb = (const float*)d_in[4];
    const float* eW1  = (const float*)d_in[5];
    const float* eb1  = (const float*)d_in[6];
    const float* eW2  = (const float*)d_in[7];
    const float* eb2  = (const float*)d_in[8];
    const float* nW1  = (const float*)d_in[9];
    const float* nb1  = (const float*)d_in[10];
    const float* nW2  = (const float*)d_in[11];
    const float* nb2  = (const float*)d_in[12];
    const float* cW1  = (const float*)d_in[13];
    const float* cb1  = (const float*)d_in[14];
    const float* cW2  = (const float*)d_in[15];
    const float* cb2  = (const float*)d_in[16];
    const int* erow = ei;
    const int* ecol = ei + EE;
    float* out = (float*)d_out;

    void* p;
    float *pU, *pV, *pZ, *pM, *pT, *pH0, *pH1, *pX0, *pX1, *pDeg;
    cudaGetSymbolAddress(&p, g_U);    pU  = (float*)p;
    cudaGetSymbolAddress(&p, g_V);    pV  = (float*)p;
    cudaGetSymbolAddress(&p, g_Zsum); pZ  = (float*)p;
    cudaGetSymbolAddress(&p, g_M);    pM  = (float*)p;
    cudaGetSymbolAddress(&p, g_T);    pT  = (float*)p;
    cudaGetSymbolAddress(&p, g_h0);   pH0 = (float*)p;
    cudaGetSymbolAddress(&p, g_h1);   pH1 = (float*)p;
    cudaGetSymbolAddress(&p, g_x0);   pX0 = (float*)p;
    cudaGetSymbolAddress(&p, g_x1);   pX1 = (float*)p;
    cudaGetSymbolAddress(&p, g_deg);  pDeg = (float*)p;

    cudaFuncSetAttribute(edge_kernel, cudaFuncAttributeMaxDynamicSharedMemorySize,
                         EDGE_SMEM_BYTES);

    // ---- per-call precompute ----
    cudaMemsetAsync(pDeg, 0, NN * sizeof(float));
    deg_kernel<<<EE / 256, 256>>>(erow);
    precompD_kernel<<<HH, HH>>>(eW2, cW1, eb2, cb1);
    wuv_kernel<<<HH, HH>>>(eW1, eb1);
    embed_kernel<<<157, 128>>>(h, embW, embb, NN);
    cudaMemcpyAsync(pX0, x, NN * 3 * sizeof(float), cudaMemcpyDeviceToDevice);

    const int GB = NN / RPB;  // 625

    for (int l = 0; l < 2; l++) {
        const float* hi = (l == 0) ? pH0 : pH1;
        float*       ho = (l == 0) ? pH1 : out;
        const float* xi = (l == 0) ? pX0 : pX1;
        float*       xo = (l == 0) ? pX1 : out + (size_t)NN * HH;

        cudaMemsetAsync(pZ, 0, (size_t)NN * HH * sizeof(float));
        cudaMemcpyAsync(xo, xi, NN * 3 * sizeof(float), cudaMemcpyDeviceToDevice);

        gemm_uv<<<GB, 256>>>(hi, pU, pV);
        edge_kernel<<<GRIDP, 256, EDGE_SMEM_BYTES>>>(erow, ecol, xi, eW1 + 256 * HH,
                                                     cW2, cb2, xo);
        gemm128<false, false, false, true><<<GB, HH>>>(pZ, eW2, nullptr, nullptr,
                                                       eb2, pDeg, nullptr, pM);
        gemm128<true, true, false, false><<<GB, HH>>>(hi, nW1, pM, nW1 + HH * HH,
                                                      nb1, nullptr, nullptr, pT);
        gemm128<false, false, true, false><<<GB, HH>>>(pT, nW2, nullptr, nullptr,
                                                       nb2, nullptr, hi, ho);
    }
    (void)in_sizes; (void)n_in; (void)out_size;
}

// round 10
// speedup vs baseline: 1.2110x; 1.1575x over previous
#include <cuda_runtime.h>
#include <cuda_fp16.h>
#include <cstdint>

#define NN 20000
#define EE 640000
#define HH 128
#define NTILES 5000             // 128-edge tiles
#define GRIDP 148
#define RPB 32
#define SA 68                   // zs stride (u32 words per edge row): 68%32==4 -> conflict-free
#define SD 68                   // Dt stride (u32 words per n row)

// ---- smem word offsets ----
#define OFF_DT  0                         // 128 x SD u32 (half2 D^T)
#define OFF_ZS  (128 * SD)                // 2 buffers x 128 x SA u32
#define OFF_SDV (OFF_ZS + 2 * 128 * SA)
#define OFF_SC2 (OFF_SDV + 128)
#define OFF_SW3 (OFF_SC2 + 128)
#define OFF_GEO (OFF_SW3 + 128)           // 3 x 768 words
#define EDGE_SMEM_WORDS (OFF_GEO + 3 * 768)
#define EDGE_SMEM_BYTES (EDGE_SMEM_WORDS * 4)

// ---------------- scratch ----------------
__device__ float g_U[NN * HH];
__device__ float g_V[NN * HH];
__device__ float g_Zsum[NN * HH];
__device__ float g_M[NN * HH];
__device__ float g_T[NN * HH];
__device__ float g_h0[NN * HH];
__device__ float g_h1[NN * HH];
__device__ float g_x0[NN * 3];
__device__ float g_x1[NN * 3];
__device__ float g_deg[NN];
__device__ float g_D[HH * HH];    // eW2 @ cW1
__device__ float g_dvec[HH];      // eb2 @ cW1 + cb1
__device__ float g_Wuv[HH * 256];
__device__ float g_buv[256];

// ---------------- degree ----------------
__global__ void deg_kernel(const int* __restrict__ erow) {
    int e = blockIdx.x * 256 + threadIdx.x;
    if (e < EE) atomicAdd(&g_deg[erow[e]], 1.0f);
}

// ---------------- D = eW2 @ cW1, dvec = eb2 @ cW1 + cb1 ----------------
__global__ void precompD_kernel(const float* __restrict__ eW2, const float* __restrict__ cW1,
                                const float* __restrict__ eb2, const float* __restrict__ cb1) {
    int a = blockIdx.x, j = threadIdx.x;
    float s = 0.f;
#pragma unroll 8
    for (int m = 0; m < HH; m++)
        s = fmaf(__ldg(&eW2[a * HH + m]), __ldg(&cW1[m * HH + j]), s);
    g_D[a * HH + j] = s;
    if (a == 0) {
        float t = __ldg(&cb1[j]);
#pragma unroll 8
        for (int m = 0; m < HH; m++)
            t = fmaf(__ldg(&eb2[m]), __ldg(&cW1[m * HH + j]), t);
        g_dvec[j] = t;
    }
}

__global__ void wuv_kernel(const float* __restrict__ eW1, const float* __restrict__ eb1) {
    int k = blockIdx.x, j = threadIdx.x;
    g_Wuv[k * 256 + j] = eW1[k * HH + j];
    g_Wuv[k * 256 + 128 + j] = eW1[(HH + k) * HH + j];
    if (k == 0) {
        g_buv[j] = eb1[j];
        g_buv[128 + j] = 0.f;
    }
}

// ---------------- embed ----------------
__global__ void __launch_bounds__(128)
embed_kernel(const float* __restrict__ hin, const float* __restrict__ W,
             const float* __restrict__ b, int nrows) {
    __shared__ float sW[16 * HH];
    __shared__ float sH[128 * 16];
    const int tid = threadIdx.x;
    const int r0 = blockIdx.x * 128;
#pragma unroll
    for (int it = 0; it < 16; it++)
        sW[tid + it * 128] = __ldg(&W[tid + it * 128]);
#pragma unroll
    for (int it = 0; it < 4; it++) {
        int l = tid + it * 128;
        int row = l >> 2, c4 = l & 3;
        int gr = r0 + row;
        if (gr >= nrows) gr = nrows - 1;
        float4 v = __ldg((const float4*)(hin + (size_t)gr * 16) + c4);
        *(float4*)(sH + row * 16 + c4 * 4) = v;
    }
    __syncthreads();
    const float bj = __ldg(&b[tid]);
#pragma unroll 1
    for (int rr = 0; rr < 128; rr++) {
        int gr = r0 + rr;
        if (gr >= nrows) break;
        float acc = bj;
#pragma unroll
        for (int k = 0; k < 16; k++)
            acc = fmaf(sH[rr * 16 + k], sW[k * HH + tid], acc);
        g_h0[(size_t)gr * HH + tid] = acc;
    }
}

// ---------------- U|V fused node GEMM ----------------
__global__ void __launch_bounds__(256)
gemm_uv(const float* __restrict__ A1, float* __restrict__ U, float* __restrict__ V) {
    __shared__ float sA[HH][36];
    const int r0 = blockIdx.x * RPB;
    const int j = threadIdx.x & 127;
    const int half_ = threadIdx.x >> 7;
#pragma unroll
    for (int ii = 0; ii < 16; ii++) {
        int i = half_ * 16 + ii;
        sA[j][i] = A1[(size_t)(r0 + i) * HH + j];
    }
    __syncthreads();

    const int jp = threadIdx.x;
    float acc[RPB];
    float b = g_buv[jp];
#pragma unroll
    for (int i = 0; i < RPB; i++) acc[i] = b;

#pragma unroll 4
    for (int k = 0; k < HH; k++) {
        float w = g_Wuv[k * 256 + jp];
#pragma unroll
        for (int i = 0; i < RPB; i += 4) {
            float4 a = *(const float4*)&sA[k][i];
            acc[i + 0] = fmaf(a.x, w, acc[i + 0]);
            acc[i + 1] = fmaf(a.y, w, acc[i + 1]);
            acc[i + 2] = fmaf(a.z, w, acc[i + 2]);
            acc[i + 3] = fmaf(a.w, w, acc[i + 3]);
        }
    }
    float* outp = (jp < 128) ? U : V;
    int jo = jp & 127;
#pragma unroll
    for (int i = 0; i < RPB; i++)
        outp[(size_t)(r0 + i) * HH + jo] = acc[i];
}

// ---------------- generic node GEMM ----------------
template <bool TWO, bool RELU, bool RESID, bool ROWSCALE>
__global__ void __launch_bounds__(128)
gemm128(const float* __restrict__ A1, const float* __restrict__ W1,
        const float* __restrict__ A2, const float* __restrict__ W2,
        const float* __restrict__ bias, const float* __restrict__ rowscale,
        const float* __restrict__ resid, float* __restrict__ C) {
    __shared__ float sA[HH][36];
    __shared__ float sB[TWO ? HH : 1][TWO ? 36 : 1];
    const int r0 = blockIdx.x * RPB;
    const int j = threadIdx.x;

#pragma unroll 8
    for (int i = 0; i < RPB; i++) sA[j][i] = A1[(size_t)(r0 + i) * HH + j];
    if (TWO) {
#pragma unroll 8
        for (int i = 0; i < RPB; i++) sB[j][i] = A2[(size_t)(r0 + i) * HH + j];
    }
    __syncthreads();

    float b = bias ? __ldg(&bias[j]) : 0.f;
    float acc[RPB];
#pragma unroll
    for (int i = 0; i < RPB; i++)
        acc[i] = ROWSCALE ? __ldg(&rowscale[r0 + i]) * b : b;

#pragma unroll 4
    for (int k = 0; k < HH; k++) {
        float w = __ldg(&W1[k * HH + j]);
#pragma unroll
        for (int i = 0; i < RPB; i += 4) {
            float4 a = *(const float4*)&sA[k][i];
            acc[i + 0] = fmaf(a.x, w, acc[i + 0]);
            acc[i + 1] = fmaf(a.y, w, acc[i + 1]);
            acc[i + 2] = fmaf(a.z, w, acc[i + 2]);
            acc[i + 3] = fmaf(a.w, w, acc[i + 3]);
        }
    }
    if (TWO) {
#pragma unroll 4
        for (int k = 0; k < HH; k++) {
            float w = __ldg(&W2[k * HH + j]);
#pragma unroll
            for (int i = 0; i < RPB; i += 4) {
                float4 a = *(const float4*)&sB[k][i];
                acc[i + 0] = fmaf(a.x, w, acc[i + 0]);
                acc[i + 1] = fmaf(a.y, w, acc[i + 1]);
                acc[i + 2] = fmaf(a.z, w, acc[i + 2]);
                acc[i + 3] = fmaf(a.w, w, acc[i + 3]);
            }
        }
    }
#pragma unroll
    for (int i = 0; i < RPB; i++) {
        float v = acc[i];
        if (RELU) v = fmaxf(v, 0.f);
        if (RESID) v += resid[(size_t)(r0 + i) * HH + j];
        C[(size_t)(r0 + i) * HH + j] = v;
    }
}

// ---------------- persistent, pipelined fused edge kernel (fp16 mma) ----------------
__global__ void __launch_bounds__(256, 1)
edge_kernel(const int* __restrict__ erow, const int* __restrict__ ecol,
            const float* __restrict__ xin, const float* __restrict__ w3,
            const float* __restrict__ cW2, const float* __restrict__ cb2,
            float* __restrict__ xout) {
    extern __shared__ float sm[];
    uint32_t* Dt = (uint32_t*)sm;                 // 128 x SD (half2)
    uint32_t* zs = Dt + 128 * SD;                 // 2 x 128 x SA (half2)
    float* sdv   = sm + OFF_SDV;
    float* sc2   = sm + OFF_SC2;
    float* sw3   = sm + OFF_SW3;
    float* srd   = sm + OFF_GEO;                  // 3 x 128 each
    float* srelx = srd + 3 * HH;
    float* srely = srelx + 3 * HH;
    float* srelz = srely + 3 * HH;
    int*   ser   = (int*)(srelz + 3 * HH);
    int*   sec   = ser + 3 * HH;

    const int tid  = threadIdx.x;
    const int lane = tid & 31;
    const int warp = tid >> 5;

    // ---- build Dt[n][k2] = half2(D[2k2][n], D[2k2+1][n]) once per block ----
#pragma unroll 4
    for (int it = 0; it < 32; it++) {
        int idx = tid + it * 256;           // 0..8191
        int n = idx >> 6, k2 = idx & 63;
        float v0 = __ldg(&g_D[(2 * k2) * HH + n]);
        float v1 = __ldg(&g_D[(2 * k2 + 1) * HH + n]);
        __half2 hp = __floats2half2_rn(v0, v1);
        Dt[n * SD + k2] = *(uint32_t*)&hp;
    }
    if (tid < HH) {
        sdv[tid] = g_dvec[tid];
        sc2[tid] = __ldg(&cW2[tid]);
        sw3[tid] = __ldg(&w3[tid]);
    }
    const float cb2v = __ldg(cb2);

    const int b = blockIdx.x;
    const int ntile = (NTILES - b + GRIDP - 1) / GRIDP;

    auto geom = [&](int i) {
        if (tid < 128) {
            int e = (b + i * GRIDP) * 128 + tid;
            int buf = (i % 3) * 128 + tid;
            int r = __ldg(&erow[e]);
            int c = __ldg(&ecol[e]);
            float dx = __ldg(&xin[3 * r + 0]) - __ldg(&xin[3 * c + 0]);
            float dy = __ldg(&xin[3 * r + 1]) - __ldg(&xin[3 * c + 1]);
            float dz = __ldg(&xin[3 * r + 2]) - __ldg(&xin[3 * c + 2]);
            ser[buf] = r; sec[buf] = c;
            srelx[buf] = dx; srely[buf] = dy; srelz[buf] = dz;
            srd[buf] = dx * dx + dy * dy + dz * dz;
        }
    };

    auto phaseA = [&](int i) {
        const int gbuf = (i % 3) * 128;
        uint32_t* z = zs + (i & 1) * 128 * SA;
        float4 w = ((const float4*)sw3)[lane];
#pragma unroll 4
        for (int ee = 0; ee < 16; ee++) {
            int eL = warp * 16 + ee;
            int r = ser[gbuf + eL], c = sec[gbuf + eL];
            float rd = srd[gbuf + eL];
            float4 u = __ldg((const float4*)(g_U + (size_t)r * HH) + lane);
            float4 v = __ldg((const float4*)(g_V + (size_t)c * HH) + lane);
            float4 zz;
            zz.x = fmaxf(u.x + v.x + rd * w.x, 0.f);
            zz.y = fmaxf(u.y + v.y + rd * w.y, 0.f);
            zz.z = fmaxf(u.z + v.z + rd * w.z, 0.f);
            zz.w = fmaxf(u.w + v.w + rd * w.w, 0.f);
            float* zp = g_Zsum + (size_t)r * HH + lane * 4;
            asm volatile("red.global.add.v4.f32 [%0], {%1, %2, %3, %4};"
                         :: "l"(zp), "f"(zz.x), "f"(zz.y), "f"(zz.z), "f"(zz.w)
                         : "memory");
            __half2 h01 = __floats2half2_rn(zz.x, zz.y);
            __half2 h23 = __floats2half2_rn(zz.z, zz.w);
            uint2 st;
            st.x = *(uint32_t*)&h01;
            st.y = *(uint32_t*)&h23;
            *(uint2*)(z + eL * SA + lane * 2) = st;
        }
    };

    auto phaseBC = [&](int i) {
        const int gbuf = (i % 3) * 128;
        const uint32_t* z = zs + (i & 1) * 128 * SA;
        const int qr = lane >> 2;
        const int lr = lane & 3;
        const int m0 = warp * 16;

        float c0[16], c1[16], c2[16], c3[16];
#pragma unroll
        for (int nt = 0; nt < 16; nt++) { c0[nt] = 0.f; c1[nt] = 0.f; c2[nt] = 0.f; c3[nt] = 0.f; }

        const uint32_t* z0 = z + (m0 + qr) * SA;
        const uint32_t* z1 = z0 + 8 * SA;

#pragma unroll
        for (int kt = 0; kt < 8; kt++) {
            const int k0 = kt * 8 + lr;
            uint32_t a0 = z0[k0];
            uint32_t a1 = z1[k0];
            uint32_t a2 = z0[k0 + 4];
            uint32_t a3 = z1[k0 + 4];
            const uint32_t* db = Dt + qr * SD + k0;
#pragma unroll
            for (int nt = 0; nt < 16; nt++) {
                uint32_t b0 = db[nt * 8 * SD];
                uint32_t b1 = db[nt * 8 * SD + 4];
                asm volatile(
                    "mma.sync.aligned.m16n8k16.row.col.f32.f16.f16.f32 "
                    "{%0,%1,%2,%3}, {%4,%5,%6,%7}, {%8,%9}, {%0,%1,%2,%3};"
                    : "+f"(c0[nt]), "+f"(c1[nt]), "+f"(c2[nt]), "+f"(c3[nt])
                    : "r"(a0), "r"(a1), "r"(a2), "r"(a3), "r"(b0), "r"(b1));
            }
        }

        float s0 = 0.f, s1 = 0.f;
#pragma unroll
        for (int nt = 0; nt < 16; nt++) {
            int j0 = nt * 8 + 2 * lr;
            float dva = sdv[j0], dvb = sdv[j0 + 1];
            float wa = sc2[j0], wb = sc2[j0 + 1];
            s0 = fmaf(fmaxf(c0[nt] + dva, 0.f), wa, s0);
            s0 = fmaf(fmaxf(c1[nt] + dvb, 0.f), wb, s0);
            s1 = fmaf(fmaxf(c2[nt] + dva, 0.f), wa, s1);
            s1 = fmaf(fmaxf(c3[nt] + dvb, 0.f), wb, s1);
        }
        s0 += __shfl_xor_sync(0xffffffffu, s0, 1);
        s0 += __shfl_xor_sync(0xffffffffu, s0, 2);
        s1 += __shfl_xor_sync(0xffffffffu, s1, 1);
        s1 += __shfl_xor_sync(0xffffffffu, s1, 2);

        if (lr == 0) {
            int eA = m0 + qr;
            int eB = eA + 8;
            float aA = s0 + cb2v;
            float aB = s1 + cb2v;
            int rA = ser[gbuf + eA], rB = ser[gbuf + eB];
            atomicAdd(&xout[3 * rA + 0], aA * srelx[gbuf + eA]);
            atomicAdd(&xout[3 * rA + 1], aA * srely[gbuf + eA]);
            atomicAdd(&xout[3 * rA + 2], aA * srelz[gbuf + eA]);
            atomicAdd(&xout[3 * rB + 0], aB * srelx[gbuf + eB]);
            atomicAdd(&xout[3 * rB + 1], aB * srely[gbuf + eB]);
            atomicAdd(&xout[3 * rB + 2], aB * srelz[gbuf + eB]);
        }
    };

    // ---- pipelined main loop ----
    if (ntile > 0) geom(0);
    __syncthreads();
    if (ntile > 0) phaseA(0);
    if (ntile > 1) geom(1);
    __syncthreads();
    for (int i = 0; i < ntile; i++) {
        if (i + 1 < ntile) phaseA(i + 1);
        if (i + 2 < ntile) geom(i + 2);
        phaseBC(i);
        __syncthreads();
    }
}

// ---------------- host launch ----------------
extern "C" void kernel_launch(void* const* d_in, const int* in_sizes, int n_in,
                              void* d_out, int out_size) {
    const float* h    = (const float*)d_in[0];
    const float* x    = (const float*)d_in[1];
    const int*   ei   = (const int*)d_in[2];
    const float* embW = (const float*)d_in[3];
    const float* embb = (const float*)d_in[4];
    const float* eW1  = (const float*)d_in[5];
    const float* eb1  = (const float*)d_in[6];
    const float* eW2  = (const float*)d_in[7];
    const float* eb2  = (const float*)d_in[8];
    const float* nW1  = (const float*)d_in[9];
    const float* nb1  = (const float*)d_in[10];
    const float* nW2  = (const float*)d_in[11];
    const float* nb2  = (const float*)d_in[12];
    const float* cW1  = (const float*)d_in[13];
    const float* cb1  = (const float*)d_in[14];
    const float* cW2  = (const float*)d_in[15];
    const float* cb2  = (const float*)d_in[16];
    const int* erow = ei;
    const int* ecol = ei + EE;
    float* out = (float*)d_out;

    void* p;
    float *pU, *pV, *pZ, *pM, *pT, *pH0, *pH1, *pX0, *pX1, *pDeg;
    cudaGetSymbolAddress(&p, g_U);    pU  = (float*)p;
    cudaGetSymbolAddress(&p, g_V);    pV  = (float*)p;
    cudaGetSymbolAddress(&p, g_Zsum); pZ  = (float*)p;
    cudaGetSymbolAddress(&p, g_M);    pM  = (float*)p;
    cudaGetSymbolAddress(&p, g_T);    pT  = (float*)p;
    cudaGetSymbolAddress(&p, g_h0);   pH0 = (float*)p;
    cudaGetSymbolAddress(&p, g_h1);   pH1 = (float*)p;
    cudaGetSymbolAddress(&p, g_x0);   pX0 = (float*)p;
    cudaGetSymbolAddress(&p, g_x1);   pX1 = (float*)p;
    cudaGetSymbolAddress(&p, g_deg);  pDeg = (float*)p;

    cudaFuncSetAttribute(edge_kernel, cudaFuncAttributeMaxDynamicSharedMemorySize,
                         EDGE_SMEM_BYTES);

    // ---- per-call precompute ----
    cudaMemsetAsync(pDeg, 0, NN * sizeof(float));
    deg_kernel<<<EE / 256, 256>>>(erow);
    precompD_kernel<<<HH, HH>>>(eW2, cW1, eb2, cb1);
    wuv_kernel<<<HH, HH>>>(eW1, eb1);
    embed_kernel<<<157, 128>>>(h, embW, embb, NN);
    cudaMemcpyAsync(pX0, x, NN * 3 * sizeof(float), cudaMemcpyDeviceToDevice);

    const int GB = NN / RPB;  // 625

    for (int l = 0; l < 2; l++) {
        const float* hi = (l == 0) ? pH0 : pH1;
        float*       ho = (l == 0) ? pH1 : out;
        const float* xi = (l == 0) ? pX0 : pX1;
        float*       xo = (l == 0) ? pX1 : out + (size_t)NN * HH;

        cudaMemsetAsync(pZ, 0, (size_t)NN * HH * sizeof(float));
        cudaMemcpyAsync(xo, xi, NN * 3 * sizeof(float), cudaMemcpyDeviceToDevice);

        gemm_uv<<<GB, 256>>>(hi, pU, pV);
        edge_kernel<<<GRIDP, 256, EDGE_SMEM_BYTES>>>(erow, ecol, xi, eW1 + 256 * HH,
                                                     cW2, cb2, xo);
        gemm128<false, false, false, true><<<GB, HH>>>(pZ, eW2, nullptr, nullptr,
                                                       eb2, pDeg, nullptr, pM);
        gemm128<true, true, false, false><<<GB, HH>>>(hi, nW1, pM, nW1 + HH * HH,
                                                      nb1, nullptr, nullptr, pT);
        gemm128<false, false, true, false><<<GB, HH>>>(pT, nW2, nullptr, nullptr,
                                                       nb2, nullptr, hi, ho);
    }
    (void)in_sizes; (void)n_in; (void)out_size;
}